// round 2
// baseline (speedup 1.0000x reference)
#include <cuda_runtime.h>
#include <cuda_bf16.h>
#include <math.h>

// Problem constants
#define NB    32
#define NPG   256
#define NNODE 8192      // NB*NPG
#define NFEAT 128
#define NHID  64
#define NCLASS 6
#define MIN_NORM 1e-15f
#define MAXN 0.996f     // (1 - PROJ_EPS)/sqrt(c)

// ---------------- scratch (device globals; no allocations allowed) ----------
__device__ float g_sx[NNODE];
__device__ float g_adj1[NB * NPG * NPG];     // 8 MB
__device__ float g_adj2[NB * 128 * 128];     // 2 MB
__device__ float g_adj3[NB * 64 * 64];       // 0.5 MB
__device__ float g_v [NNODE * NHID];
__device__ float g_tA[NNODE * NHID];
__device__ float g_tB[(NNODE/2) * NHID];
__device__ float g_hb[3 * NHID];
__device__ float g_score[NNODE];
__device__ float g_dis[NNODE];
__device__ int   g_sel [NB * 128];
__device__ float g_vals[NB * 128];
__device__ float g_a1[NB * 128];
__device__ float g_a2[NB * 128];
__device__ float g_x1[NB * 2 * NHID];
__device__ float g_x2[NB * 2 * NHID];
__device__ float g_x3[NB * 2 * NHID];

// ---------------- helpers ----------------
__device__ __forceinline__ float artanh_f(float x) {
    x = fminf(fmaxf(x, -1.0f + 1e-7f), 1.0f - 1e-7f);
    return 0.5f * (log1pf(x) - log1pf(-x));
}

__device__ __forceinline__ float block_reduce(float v, float* buf) {
    int tid = threadIdx.x;
    buf[tid] = v;
    __syncthreads();
    for (int s = blockDim.x >> 1; s > 0; s >>= 1) {
        if (tid < s) buf[tid] += buf[tid + s];
        __syncthreads();
    }
    float r = buf[0];
    __syncthreads();
    return r;
}

// ---------------- stage kernels ----------------

// per-node feature sums for edge weights
__global__ void sx_kernel(const float* __restrict__ x, float* __restrict__ sx) {
    __shared__ float buf[NFEAT];
    int i = blockIdx.x;
    float v = x[(size_t)i * NFEAT + threadIdx.x];
    float s = block_reduce(v, buf);
    if (threadIdx.x == 0) sx[i] = s;
}

__global__ void zero_kernel(float* __restrict__ p, int n) {
    for (int i = blockIdx.x * blockDim.x + threadIdx.x; i < n; i += gridDim.x * blockDim.x)
        p[i] = 0.0f;
}

// adj1[g][r%][c%] = 0.5*(sx[r]+sx[c]); duplicates write identical values -> no atomics
__global__ void scatter_kernel(const int* __restrict__ ei, int E,
                               const float* __restrict__ sx, float* __restrict__ adj1) {
    int e = blockIdx.x * blockDim.x + threadIdx.x;
    if (e >= E) return;
    int r = ei[e], c = ei[E + e];
    int g = r >> 8;  // NPG=256
    adj1[(((size_t)g * NPG) + (r & 255)) * NPG + (c & 255)] = 0.5f * (sx[r] + sx[c]);
}

// hb_l = proj(expmap0(b_l))
__global__ void hb_kernel(const float* __restrict__ b1, const float* __restrict__ b2,
                          const float* __restrict__ b3, float* __restrict__ hb) {
    __shared__ float buf[NHID];
    int l = blockIdx.x, tid = threadIdx.x;
    const float* b = (l == 0) ? b1 : (l == 1) ? b2 : b3;
    float u = b[tid];
    float un = fmaxf(sqrtf(block_reduce(u * u, buf)), MIN_NORM);
    float p = tanhf(un) / un * u;
    float pn = fmaxf(sqrtf(block_reduce(p * p, buf)), MIN_NORM);
    float f = (pn > MAXN) ? (MAXN / pn) : 1.0f;
    hb[l * NHID + tid] = p * f;
}

// v = logmap0(proj(mobius_add(proj(mobius_matvec(W, to_hyp(in))), hb)))
// one block (128 thr) per node
__global__ void pre_agg_kernel(const float* __restrict__ in, int in_dim,
                               const float* __restrict__ W,
                               const float* __restrict__ hb,
                               float* __restrict__ vout) {
    __shared__ float s_x[NFEAT];
    __shared__ float buf[128];
    int node = blockIdx.x, tid = threadIdx.x;

    float u = (tid < in_dim) ? in[(size_t)node * in_dim + tid] : 0.0f;
    // to_hyp = proj(expmap0(u))
    float un = fmaxf(sqrtf(block_reduce(u * u, buf)), MIN_NORM);
    float p = tanhf(un) / un * u;
    float pn = fmaxf(sqrtf(block_reduce(p * p, buf)), MIN_NORM);
    float xh = p * ((pn > MAXN) ? (MAXN / pn) : 1.0f);
    if (tid < in_dim) s_x[tid] = xh;
    __syncthreads();
    // mobius_matvec
    float xn = fmaxf(sqrtf(block_reduce(xh * xh, buf)), MIN_NORM);
    float mx = 0.0f;
    if (tid < NHID) {
        const float* Wr = W + (size_t)tid * in_dim;
        float acc = 0.0f;
        for (int k = 0; k < in_dim; k++) acc += Wr[k] * s_x[k];
        mx = acc;
    }
    float mxn = fmaxf(sqrtf(block_reduce(mx * mx, buf)), MIN_NORM);
    float h = tanhf(mxn / xn * artanh_f(xn)) / mxn * mx;
    // proj
    float hv = (tid < NHID) ? h : 0.0f;
    float hn = fmaxf(sqrtf(block_reduce(hv * hv, buf)), MIN_NORM);
    hv = hv * ((hn > MAXN) ? (MAXN / hn) : 1.0f);
    // mobius_add with hb
    float hbv = (tid < NHID) ? hb[tid] : 0.0f;
    float x2 = block_reduce(hv * hv, buf);
    float y2 = block_reduce(hbv * hbv, buf);
    float xy = block_reduce(hv * hbv, buf);
    float num = (1.0f + 2.0f * xy + y2) * hv + (1.0f - x2) * hbv;
    float den = fmaxf(1.0f + 2.0f * xy + x2 * y2, MIN_NORM);
    float m = num / den;
    // proj
    float mv = (tid < NHID) ? m : 0.0f;
    float mn = fmaxf(sqrtf(block_reduce(mv * mv, buf)), MIN_NORM);
    mv = mv * ((mn > MAXN) ? (MAXN / mn) : 1.0f);
    // logmap0
    float mn2 = fmaxf(sqrtf(block_reduce(mv * mv, buf)), MIN_NORM);
    if (tid < NHID) vout[(size_t)node * NHID + tid] = artanh_f(mn2) / mn2 * mv;
}

// t = logmap0(proj(expmap0(relu(logmap0(proj(expmap0(adj @ v)))))))
// one block (64 thr) per node
__global__ void agg_post_kernel(const float* __restrict__ adj, int npg,
                                const float* __restrict__ v, float* __restrict__ tout) {
    __shared__ float buf[NHID];
    int g = blockIdx.x / npg, li = blockIdx.x % npg, tid = threadIdx.x;
    const float* arow = adj + ((size_t)g * npg + li) * npg;
    const float* vg = v + (size_t)g * npg * NHID;
    float acc = 0.0f;
    for (int k = 0; k < npg; k++)
        acc += arow[k] * vg[(size_t)k * NHID + tid];
    // expmap0 + proj
    float an = fmaxf(sqrtf(block_reduce(acc * acc, buf)), MIN_NORM);
    float h = tanhf(an) / an * acc;
    float hn = fmaxf(sqrtf(block_reduce(h * h, buf)), MIN_NORM);
    h = h * ((hn > MAXN) ? (MAXN / hn) : 1.0f);
    // logmap0, relu
    float n2 = fmaxf(sqrtf(block_reduce(h * h, buf)), MIN_NORM);
    float lv = artanh_f(n2) / n2 * h;
    float r = fmaxf(lv, 0.0f);
    // expmap0 + proj
    float rn = fmaxf(sqrtf(block_reduce(r * r, buf)), MIN_NORM);
    float e = tanhf(rn) / rn * r;
    float en = fmaxf(sqrtf(block_reduce(e * e, buf)), MIN_NORM);
    e = e * ((en > MAXN) ? (MAXN / en) : 1.0f);
    // logmap0
    float n3 = fmaxf(sqrtf(block_reduce(e * e, buf)), MIN_NORM);
    tout[((size_t)g * npg + li) * NHID + tid] = artanh_f(n3) / n3 * e;
}

__global__ void deg_kernel(const float* __restrict__ adj, int npg,
                           float* __restrict__ dis, int n) {
    int i = blockIdx.x * blockDim.x + threadIdx.x;
    if (i >= n) return;
    int g = i / npg, li = i % npg;
    const float* arow = adj + ((size_t)g * npg + li) * npg;
    float s = 0.0f;
    for (int k = 0; k < npg; k++) s += arow[k];
    dis[i] = (s > 0.0f) ? (1.0f / sqrtf(s)) : 0.0f;
}

// score[i] = sum_d | t[i][d] - dis[i] * sum_k adj[i][k]*dis[k]*t[k][d] |
__global__ void score_kernel(const float* __restrict__ adj, int npg,
                             const float* __restrict__ t, const float* __restrict__ dis,
                             float* __restrict__ score) {
    __shared__ float buf[NHID];
    int g = blockIdx.x / npg, li = blockIdx.x % npg, tid = threadIdx.x;
    const float* arow = adj + ((size_t)g * npg + li) * npg;
    float acc = 0.0f;
    for (int k = 0; k < npg; k++)
        acc += arow[k] * dis[g * npg + k] * t[((size_t)g * npg + k) * NHID + tid];
    float prop = dis[g * npg + li] * acc;
    float diff = fabsf(t[((size_t)g * npg + li) * NHID + tid] - prop);
    float s = block_reduce(diff, buf);
    if (tid == 0) score[g * npg + li] = s;
}

// per-graph bitonic sort, descending score, ties -> lower index first
__global__ void topk_kernel(const float* __restrict__ score, int npg, int k,
                            int* __restrict__ sel, float* __restrict__ vals) {
    __shared__ float s[256];
    __shared__ int   id[256];
    int g = blockIdx.x, tid = threadIdx.x;
    s[tid] = score[g * npg + tid];
    id[tid] = tid;
    __syncthreads();
    for (int ksz = 2; ksz <= npg; ksz <<= 1) {
        for (int j = ksz >> 1; j > 0; j >>= 1) {
            int i = tid, ixj = i ^ j;
            if (ixj > i) {
                bool asc = ((i & ksz) == 0);
                float si = s[i], sj = s[ixj];
                int ii = id[i], ij = id[ixj];
                // ordering: larger score first; equal -> smaller index first
                bool i_after_j = (si < sj) || (si == sj && ii > ij);
                if (i_after_j == asc) { s[i] = sj; s[ixj] = si; id[i] = ij; id[ixj] = ii; }
            }
            __syncthreads();
        }
    }
    if (tid < k) { sel[g * k + tid] = id[tid]; vals[g * k + tid] = s[tid]; }
}

// xn = t_old[sel] * tanh(val); a1 = xn.att[:64]; a2 = xn.att[64:]
__global__ void pool_feat_kernel(const float* __restrict__ t_old, int npg, int k,
                                 const int* __restrict__ sel, const float* __restrict__ vals,
                                 const float* __restrict__ att,
                                 float* __restrict__ t_new,
                                 float* __restrict__ a1, float* __restrict__ a2) {
    __shared__ float buf[NHID];
    int g = blockIdx.x / k, i = blockIdx.x % k, tid = threadIdx.x;
    int li = sel[g * k + i];
    float tn = tanhf(vals[g * k + i]);
    float xv = t_old[((size_t)g * npg + li) * NHID + tid] * tn;
    t_new[((size_t)g * k + i) * NHID + tid] = xv;
    float r1 = block_reduce(xv * att[tid], buf);
    float r2 = block_reduce(xv * att[NHID + tid], buf);
    if (tid == 0) { a1[g * k + i] = r1; a2[g * k + i] = r2; }
}

// new_adj[i][j] = max(a1_i + a2_j, 0) + adj_old[sel_i][sel_j]   (within graph)
__global__ void new_adj_kernel(const float* __restrict__ adj_old, int npg, int k,
                               const int* __restrict__ sel,
                               const float* __restrict__ a1, const float* __restrict__ a2,
                               float* __restrict__ adj_new) {
    int g = blockIdx.x / k, i = blockIdx.x % k, j = threadIdx.x;
    int si = sel[g * k + i], sj = sel[g * k + j];
    float e = a1[g * k + i] + a2[g * k + j];
    float val = fmaxf(e, 0.0f) + adj_old[((size_t)g * npg + si) * npg + sj];
    adj_new[((size_t)g * k + i) * k + j] = val;
}

// per-graph concat(max over nodes, mean over nodes)
__global__ void readout_kernel(const float* __restrict__ t, int k, float* __restrict__ out) {
    int g = blockIdx.x, d = threadIdx.x;  // 64 threads
    float mx = -INFINITY, sm = 0.0f;
    for (int i = 0; i < k; i++) {
        float v = t[((size_t)g * k + i) * NHID + d];
        mx = fmaxf(mx, v);
        sm += v;
    }
    out[g * 2 * NHID + d] = mx;
    out[g * 2 * NHID + NHID + d] = sm / (float)k;
}

__global__ void mlp_kernel(const float* __restrict__ x1, const float* __restrict__ x2,
                           const float* __restrict__ x3,
                           const float* __restrict__ lw1, const float* __restrict__ lb1,
                           const float* __restrict__ lw2, const float* __restrict__ lb2,
                           const float* __restrict__ lw3, const float* __restrict__ lb3,
                           float* __restrict__ out) {
    __shared__ float r0[2 * NHID];
    __shared__ float r1[NHID];
    __shared__ float r2[NHID / 2];
    int g = blockIdx.x, tid = threadIdx.x;  // 128 threads
    {
        float a = fmaxf(x1[g * 128 + tid], 0.0f) + fmaxf(x2[g * 128 + tid], 0.0f)
                + fmaxf(x3[g * 128 + tid], 0.0f);
        r0[tid] = a;
    }
    __syncthreads();
    if (tid < NHID) {
        float acc = lb1[tid];
        for (int k = 0; k < 128; k++) acc += lw1[tid * 128 + k] * r0[k];
        r1[tid] = fmaxf(acc, 0.0f);
    }
    __syncthreads();
    if (tid < 32) {
        float acc = lb2[tid];
        for (int k = 0; k < 64; k++) acc += lw2[tid * 64 + k] * r1[k];
        r2[tid] = fmaxf(acc, 0.0f);
    }
    __syncthreads();
    if (tid == 0) {
        float l[NCLASS];
        float m = -INFINITY;
        for (int j = 0; j < NCLASS; j++) {
            float acc = lb3[j];
            for (int k = 0; k < 32; k++) acc += lw3[j * 32 + k] * r2[k];
            l[j] = acc;
            m = fmaxf(m, acc);
        }
        float s = 0.0f;
        for (int j = 0; j < NCLASS; j++) s += expf(l[j] - m);
        float lse = m + logf(s);
        for (int j = 0; j < NCLASS; j++) out[g * NCLASS + j] = l[j] - lse;
    }
}

// ---------------- launch ----------------
extern "C" void kernel_launch(void* const* d_in, const int* in_sizes, int n_in,
                              void* d_out, int out_size) {
    const float* x    = (const float*)d_in[0];
    const int*   ei   = (const int*)d_in[1];
    const float* W1   = (const float*)d_in[2];
    const float* b1   = (const float*)d_in[3];
    const float* W2   = (const float*)d_in[4];
    const float* b2   = (const float*)d_in[5];
    const float* W3   = (const float*)d_in[6];
    const float* b3   = (const float*)d_in[7];
    const float* att1 = (const float*)d_in[8];
    const float* att2 = (const float*)d_in[9];
    const float* lw1  = (const float*)d_in[10];
    const float* lb1  = (const float*)d_in[11];
    const float* lw2  = (const float*)d_in[12];
    const float* lb2  = (const float*)d_in[13];
    const float* lw3  = (const float*)d_in[14];
    const float* lb3  = (const float*)d_in[15];

    int E = in_sizes[1] / 2;

    float *sx, *adj1, *adj2, *adj3, *v, *tA, *tB, *hb, *score, *dis, *vals, *a1, *a2, *x1b, *x2b, *x3b;
    int* sel;
    cudaGetSymbolAddress((void**)&sx,   g_sx);
    cudaGetSymbolAddress((void**)&adj1, g_adj1);
    cudaGetSymbolAddress((void**)&adj2, g_adj2);
    cudaGetSymbolAddress((void**)&adj3, g_adj3);
    cudaGetSymbolAddress((void**)&v,    g_v);
    cudaGetSymbolAddress((void**)&tA,   g_tA);
    cudaGetSymbolAddress((void**)&tB,   g_tB);
    cudaGetSymbolAddress((void**)&hb,   g_hb);
    cudaGetSymbolAddress((void**)&score,g_score);
    cudaGetSymbolAddress((void**)&dis,  g_dis);
    cudaGetSymbolAddress((void**)&sel,  g_sel);
    cudaGetSymbolAddress((void**)&vals, g_vals);
    cudaGetSymbolAddress((void**)&a1,   g_a1);
    cudaGetSymbolAddress((void**)&a2,   g_a2);
    cudaGetSymbolAddress((void**)&x1b,  g_x1);
    cudaGetSymbolAddress((void**)&x2b,  g_x2);
    cudaGetSymbolAddress((void**)&x3b,  g_x3);

    // ---- build adj1 ----
    sx_kernel<<<NNODE, NFEAT>>>(x, sx);
    zero_kernel<<<4096, 512>>>(adj1, NB * NPG * NPG);
    scatter_kernel<<<(E + 255) / 256, 256>>>(ei, E, sx, adj1);
    hb_kernel<<<3, NHID>>>(b1, b2, b3, hb);

    // ---- layer 1 (8192 nodes, in_dim 128) ----
    pre_agg_kernel<<<NNODE, 128>>>(x, NFEAT, W1, hb, v);
    agg_post_kernel<<<NNODE, NHID>>>(adj1, NPG, v, tA);
    deg_kernel<<<(NNODE + 127) / 128, 128>>>(adj1, NPG, dis, NNODE);
    score_kernel<<<NNODE, NHID>>>(adj1, NPG, tA, dis, score);
    topk_kernel<<<NB, NPG>>>(score, NPG, 128, sel, vals);
    pool_feat_kernel<<<NB * 128, NHID>>>(tA, NPG, 128, sel, vals, att1, tB, a1, a2);
    new_adj_kernel<<<NB * 128, 128>>>(adj1, NPG, 128, sel, a1, a2, adj2);
    readout_kernel<<<NB, NHID>>>(tB, 128, x1b);

    // ---- layer 2 (4096 nodes, in_dim 64) ----
    pre_agg_kernel<<<NB * 128, 128>>>(tB, NHID, W2, hb + NHID, v);
    agg_post_kernel<<<NB * 128, NHID>>>(adj2, 128, v, tA);
    deg_kernel<<<(NB * 128 + 127) / 128, 128>>>(adj2, 128, dis, NB * 128);
    score_kernel<<<NB * 128, NHID>>>(adj2, 128, tA, dis, score);
    topk_kernel<<<NB, 128>>>(score, 128, 64, sel, vals);
    pool_feat_kernel<<<NB * 64, NHID>>>(tA, 128, 64, sel, vals, att2, tB, a1, a2);
    new_adj_kernel<<<NB * 64, 64>>>(adj2, 128, 64, sel, a1, a2, adj3);
    readout_kernel<<<NB, NHID>>>(tB, 64, x2b);

    // ---- layer 3 (2048 nodes, in_dim 64) ----
    pre_agg_kernel<<<NB * 64, 128>>>(tB, NHID, W3, hb + 2 * NHID, v);
    agg_post_kernel<<<NB * 64, NHID>>>(adj3, 64, v, tA);
    readout_kernel<<<NB, NHID>>>(tA, 64, x3b);

    // ---- MLP head ----
    mlp_kernel<<<NB, 128>>>(x1b, x2b, x3b, lw1, lb1, lw2, lb2, lw3, lb3, (float*)d_out);
}